// round 2
// baseline (speedup 1.0000x reference)
#include <cuda_runtime.h>
#include <cstdint>

// Problem constants
#define NN 50000
#define NE 800000
#define DH 64

// Scratch (device globals: no allocation allowed)
__device__ float g_h[NN * DH];     // node features (current block input)
__device__ float g_A[NN * DH];     // h @ w0[:64]   (src half)
__device__ float g_B[NN * DH];     // h @ w0[64:]   (dst half)
__device__ float g_agg[NN * DH];   // scatter-accumulated u
__device__ float g_deg[NN];        // in-degree (float)
__device__ int   g_is64;           // edge_index dtype flag (1 = int64, 0 = int32)

// Packed fp32x2 FMA (sm_100+; only reachable via PTX)
__device__ __forceinline__ void ffma2(unsigned long long& d,
                                      unsigned long long a,
                                      unsigned long long b) {
    asm("fma.rn.f32x2 %0, %1, %2, %0;" : "+l"(d) : "l"(a), "l"(b));
}

// ---------------------------------------------------------------------------
// Detect whether edge_index is int64 or int32 (JAX may silently emit int32).
// ---------------------------------------------------------------------------
__global__ void detect_kernel(const int* __restrict__ ei32) {
    __shared__ int any;
    if (threadIdx.x == 0) any = 0;
    __syncthreads();
    for (int i = threadIdx.x; i < 4096; i += 256) {
        if (ei32[2 * i + 1] != 0) any = 1;  // benign race
    }
    __syncthreads();
    if (threadIdx.x == 0) g_is64 = (any == 0) ? 1 : 0;
}

__device__ __forceinline__ void load_edge(const void* ei, int e, int& src, int& dst) {
    if (g_is64) {
        const long long* p = (const long long*)ei;
        src = (int)p[e];
        dst = (int)p[NE + e];
    } else {
        const int* p = (const int*)ei;
        src = p[e];
        dst = p[NE + e];
    }
}

// ---------------------------------------------------------------------------
// h = x @ lin_in_w + lin_in_b   ([50000,16] @ [16,64])
// ---------------------------------------------------------------------------
__global__ void lin_in_kernel(const float* __restrict__ x,
                              const float* __restrict__ w,
                              const float* __restrict__ b) {
    __shared__ float ws[16 * 64];
    __shared__ float bs[64];
    __shared__ float xs[4][16];
    int tid = threadIdx.x;
    for (int i = tid; i < 16 * 64; i += 256) ws[i] = w[i];
    if (tid < 64) bs[tid] = b[tid];
    if (tid < 64) {
        int nl = tid >> 4, c = tid & 15;
        int n = blockIdx.x * 4 + nl;
        xs[nl][c] = x[n * 16 + c];
    }
    __syncthreads();
    int j = tid & 63, nl = tid >> 6;
    int n = blockIdx.x * 4 + nl;
    float acc = bs[j];
#pragma unroll
    for (int c = 0; c < 16; c++) acc = fmaf(xs[nl][c], ws[c * 64 + j], acc);
    g_h[n * 64 + j] = acc;
}

// ---------------------------------------------------------------------------
// Degree + zero helpers
// ---------------------------------------------------------------------------
__global__ void zero_deg_kernel() {
    int i = blockIdx.x * 256 + threadIdx.x;
    if (i < NN) g_deg[i] = 0.0f;
}

__global__ void count_deg_kernel(const void* __restrict__ ei) {
    int e = blockIdx.x * 256 + threadIdx.x;
    int src, dst;
    load_edge(ei, e, src, dst);
    atomicAdd(&g_deg[dst], 1.0f);
}

__global__ void zero_agg_kernel() {
    int i = blockIdx.x * 256 + threadIdx.x;
    g_agg[i] = 0.0f;
}

// ---------------------------------------------------------------------------
// A = h @ w0[0:64,:],  B = h @ w0[64:128,:]
// ---------------------------------------------------------------------------
__global__ __launch_bounds__(256) void nodeAB_kernel(const float* __restrict__ w0k) {
    __shared__ float w0s[128 * 64];  // 32 KB
    __shared__ float hs[16][64];
    int tid = threadIdx.x;
    for (int i = tid; i < 128 * 64; i += 256) w0s[i] = w0k[i];
    int n0 = blockIdx.x * 16;
    for (int i = tid; i < 16 * 64; i += 256)
        hs[i >> 6][i & 63] = g_h[(n0 + (i >> 6)) * 64 + (i & 63)];
    __syncthreads();
    int j = tid & 63, grp = tid >> 6;
    float a[4] = {0, 0, 0, 0}, bb[4] = {0, 0, 0, 0};
#pragma unroll 8
    for (int c = 0; c < 64; c++) {
        float wa = w0s[c * 64 + j];
        float wb = w0s[(64 + c) * 64 + j];
#pragma unroll
        for (int i = 0; i < 4; i++) {
            float hv = hs[grp * 4 + i][c];
            a[i]  = fmaf(hv, wa, a[i]);
            bb[i] = fmaf(hv, wb, bb[i]);
        }
    }
#pragma unroll
    for (int i = 0; i < 4; i++) {
        int n = n0 + grp * 4 + i;
        g_A[n * 64 + j] = a[i];
        g_B[n * 64 + j] = bb[i];
    }
}

// ---------------------------------------------------------------------------
// Edge kernel: 4 threads per edge, packed f32x2 FMA.
//   t = relu(A[src] + B[dst] + b0)   — each lane computes a 16-wide quarter,
//       staged in SMEM (68-word edge stride, 17-word quarter stride:
//       conflict-free for both scalar STS writes and broadcast LDS reads)
//   u = relu(t @ w1 + b1)            — each lane computes 16 outputs as 8
//       f32x2 accumulators; w1 in SMEM with 80/20-word padded layout so the
//       four quarter LDS.128s hit disjoint bank groups
//   agg[dst] += u                    — red.global.add.v4.f32 (4 per lane)
// Block 256 threads = 64 edges. Grid 12500 (exact).
// ---------------------------------------------------------------------------
__global__ __launch_bounds__(256) void edge_kernel(const void* __restrict__ ei,
                                                   const float* __restrict__ w1,
                                                   const float* __restrict__ b0,
                                                   const float* __restrict__ b1) {
    __shared__ __align__(16) float w1s[64 * 80];    // 20.5 KB padded
    __shared__ __align__(16) float b0s[64];
    __shared__ __align__(16) float b1s[64];
    __shared__ __align__(16) float ts[8 * 544];     // 8 warps x 8 edges x 68

    int tid = threadIdx.x;
    for (int i = tid; i < 64 * 64; i += 256) {
        int k = i >> 6, j = i & 63;
        w1s[80 * k + 20 * (j >> 4) + (j & 15)] = w1[i];
    }
    if (tid < 64) { b0s[tid] = b0[tid]; b1s[tid] = b1[tid]; }
    __syncthreads();

    int lane = tid & 31, warp = tid >> 5;
    int e8 = lane >> 2;      // edge within warp (0..7)
    int q  = lane & 3;       // quarter (0..3)
    int e = blockIdx.x * 64 + warp * 8 + e8;
    int src, dst;
    load_edge(ei, e, src, dst);

    // --- gather + t quarter ---
    const float4* Ar = (const float4*)(g_A + src * 64 + q * 16);
    const float4* Br = (const float4*)(g_B + dst * 64 + q * 16);
    float4 av[4], bv[4];
#pragma unroll
    for (int i = 0; i < 4; i++) { av[i] = __ldg(&Ar[i]); bv[i] = __ldg(&Br[i]); }

    float* twe = ts + warp * 544 + e8 * 68;   // this edge's t row
    float* twq = twe + q * 17;                // this lane's quarter (write)
#pragma unroll
    for (int i = 0; i < 4; i++) {
        const float* c = b0s + q * 16 + 4 * i;
        twq[4 * i + 0] = fmaxf(av[i].x + bv[i].x + c[0], 0.0f);
        twq[4 * i + 1] = fmaxf(av[i].y + bv[i].y + c[1], 0.0f);
        twq[4 * i + 2] = fmaxf(av[i].z + bv[i].z + c[2], 0.0f);
        twq[4 * i + 3] = fmaxf(av[i].w + bv[i].w + c[3], 0.0f);
    }
    __syncwarp();

    // --- u quarter = relu(t @ w1 + b1) with packed f32x2 ---
    unsigned long long u[8];
    const unsigned long long* b1q = (const unsigned long long*)(b1s + q * 16);
#pragma unroll
    for (int i = 0; i < 8; i++) u[i] = b1q[i];

#pragma unroll
    for (int k = 0; k < 64; k++) {
        float tk = twe[17 * (k >> 4) + (k & 15)];   // broadcast LDS.32
        unsigned long long tk2;
        asm("mov.b64 %0, {%1, %2};" : "=l"(tk2) : "f"(tk), "f"(tk));
        const ulonglong2* wp = (const ulonglong2*)(w1s + 80 * k + 20 * q);
#pragma unroll
        for (int i = 0; i < 4; i++) {
            ulonglong2 wv = wp[i];                  // LDS.128, conflict-free
            ffma2(u[2 * i + 0], tk2, wv.x);
            ffma2(u[2 * i + 1], tk2, wv.y);
        }
    }

    // --- relu + scatter ---
    float* outp = g_agg + dst * 64 + q * 16;
#pragma unroll
    for (int i = 0; i < 4; i++) {
        float2 p0 = *reinterpret_cast<float2*>(&u[2 * i + 0]);
        float2 p1 = *reinterpret_cast<float2*>(&u[2 * i + 1]);
        float r0 = fmaxf(p0.x, 0.0f), r1 = fmaxf(p0.y, 0.0f);
        float r2 = fmaxf(p1.x, 0.0f), r3 = fmaxf(p1.y, 0.0f);
        float* d4 = outp + 4 * i;
        asm volatile("red.global.add.v4.f32 [%0], {%1, %2, %3, %4};"
                     :: "l"(d4), "f"(r0), "f"(r1), "f"(r2), "f"(r3)
                     : "memory");
    }
}

// ---------------------------------------------------------------------------
// h = agg @ w2 + deg * b2   ([50000,64] @ [64,64])
// ---------------------------------------------------------------------------
__global__ __launch_bounds__(256) void nodeOut_kernel(const float* __restrict__ w2k,
                                                      const float* __restrict__ b2k) {
    __shared__ float ws[64 * 64];
    __shared__ float hs[16][64];
    __shared__ float bs[64];
    int tid = threadIdx.x;
    for (int i = tid; i < 64 * 64; i += 256) ws[i] = w2k[i];
    if (tid < 64) bs[tid] = b2k[tid];
    int n0 = blockIdx.x * 16;
    for (int i = tid; i < 16 * 64; i += 256)
        hs[i >> 6][i & 63] = g_agg[(n0 + (i >> 6)) * 64 + (i & 63)];
    __syncthreads();
    int j = tid & 63, grp = tid >> 6;
    float acc[4];
#pragma unroll
    for (int i = 0; i < 4; i++) acc[i] = g_deg[n0 + grp * 4 + i] * bs[j];
#pragma unroll 8
    for (int c = 0; c < 64; c++) {
        float wv = ws[c * 64 + j];
#pragma unroll
        for (int i = 0; i < 4; i++)
            acc[i] = fmaf(hs[grp * 4 + i][c], wv, acc[i]);
    }
#pragma unroll
    for (int i = 0; i < 4; i++)
        g_h[(n0 + grp * 4 + i) * 64 + j] = acc[i];
}

// ---------------------------------------------------------------------------
// out = h @ lin_out_w + lin_out_b   ([50000,64] @ [64,16])
// ---------------------------------------------------------------------------
__global__ void lin_out_kernel(const float* __restrict__ w,
                               const float* __restrict__ b,
                               float* __restrict__ out) {
    __shared__ float ws[64 * 16];
    __shared__ float bs[16];
    __shared__ float hs[16][64];
    int tid = threadIdx.x;
    for (int i = tid; i < 64 * 16; i += 256) ws[i] = w[i];
    if (tid < 16) bs[tid] = b[tid];
    int n0 = blockIdx.x * 16;
    for (int i = tid; i < 16 * 64; i += 256)
        hs[i >> 6][i & 63] = g_h[(n0 + (i >> 6)) * 64 + (i & 63)];
    __syncthreads();
    int j = tid & 15, nl = tid >> 4;
    float acc = bs[j];
#pragma unroll 16
    for (int c = 0; c < 64; c++)
        acc = fmaf(hs[nl][c], ws[c * 16 + j], acc);
    out[(n0 + nl) * 16 + j] = acc;
}

// ---------------------------------------------------------------------------
// Launch
// ---------------------------------------------------------------------------
extern "C" void kernel_launch(void* const* d_in, const int* in_sizes, int n_in,
                              void* d_out, int out_size) {
    const float* x        = (const float*)d_in[0];
    // d_in[1] = lframes (unused by the reference)
    const void*  ei       = d_in[2];
    const float* lin_in_w = (const float*)d_in[3];
    const float* lin_in_b = (const float*)d_in[4];
    const float* w0       = (const float*)d_in[5];
    const float* b0       = (const float*)d_in[6];
    const float* w1       = (const float*)d_in[7];
    const float* b1       = (const float*)d_in[8];
    const float* w2       = (const float*)d_in[9];
    const float* b2       = (const float*)d_in[10];
    const float* low      = (const float*)d_in[11];
    const float* lob      = (const float*)d_in[12];
    float* out = (float*)d_out;

    detect_kernel<<<1, 256>>>((const int*)ei);
    lin_in_kernel<<<NN / 4, 256>>>(x, lin_in_w, lin_in_b);
    zero_deg_kernel<<<(NN + 255) / 256, 256>>>();
    count_deg_kernel<<<NE / 256, 256>>>(ei);

    for (int k = 0; k < 4; k++) {
        nodeAB_kernel<<<NN / 16, 256>>>(w0 + k * 128 * 64);
        zero_agg_kernel<<<NN * 64 / 256, 256>>>();
        edge_kernel<<<NE / 64, 256>>>(ei, w1 + k * 64 * 64, b0 + k * 64, b1 + k * 64);
        nodeOut_kernel<<<NN / 16, 256>>>(w2 + k * 64 * 64, b2 + k * 64);
    }

    lin_out_kernel<<<NN / 16, 256>>>(low, lob, out);
}

// round 5
// speedup vs baseline: 1.2995x; 1.2995x over previous
#include <cuda_runtime.h>
#include <cstdint>

// Problem constants
#define NN 50000
#define NE 800000
#define DH 64

// Scratch (device globals: no allocation allowed)
__device__ float g_h[NN * DH];     // node features (current block input)
__device__ float g_A[NN * DH];     // h @ w0[:64]   (src half)
__device__ float g_B[NN * DH];     // h @ w0[64:]   (dst half)
__device__ float g_agg[NN * DH];   // scatter-accumulated u
__device__ float g_deg[NN];        // in-degree (float)
__device__ int   g_is64;           // edge_index dtype flag (1 = int64, 0 = int32)

// Packed fp32x2 FMA (sm_100+; only reachable via PTX)
__device__ __forceinline__ void ffma2(unsigned long long& d,
                                      unsigned long long a,
                                      unsigned long long b) {
    asm("fma.rn.f32x2 %0, %1, %2, %0;" : "+l"(d) : "l"(a), "l"(b));
}

// ---------------------------------------------------------------------------
// Detect whether edge_index is int64 or int32 (JAX may silently emit int32).
// ---------------------------------------------------------------------------
__global__ void detect_kernel(const int* __restrict__ ei32) {
    __shared__ int any;
    if (threadIdx.x == 0) any = 0;
    __syncthreads();
    for (int i = threadIdx.x; i < 4096; i += 256) {
        if (ei32[2 * i + 1] != 0) any = 1;  // benign race
    }
    __syncthreads();
    if (threadIdx.x == 0) g_is64 = (any == 0) ? 1 : 0;
}

__device__ __forceinline__ void load_edge(const void* ei, int e, int& src, int& dst) {
    if (g_is64) {
        const long long* p = (const long long*)ei;
        src = (int)p[e];
        dst = (int)p[NE + e];
    } else {
        const int* p = (const int*)ei;
        src = p[e];
        dst = p[NE + e];
    }
}

// ---------------------------------------------------------------------------
// h = x @ lin_in_w + lin_in_b   ([50000,16] @ [16,64])
// ---------------------------------------------------------------------------
__global__ void lin_in_kernel(const float* __restrict__ x,
                              const float* __restrict__ w,
                              const float* __restrict__ b) {
    __shared__ float ws[16 * 64];
    __shared__ float bs[64];
    __shared__ float xs[4][16];
    int tid = threadIdx.x;
    for (int i = tid; i < 16 * 64; i += 256) ws[i] = w[i];
    if (tid < 64) bs[tid] = b[tid];
    if (tid < 64) {
        int nl = tid >> 4, c = tid & 15;
        int n = blockIdx.x * 4 + nl;
        xs[nl][c] = x[n * 16 + c];
    }
    __syncthreads();
    int j = tid & 63, nl = tid >> 6;
    int n = blockIdx.x * 4 + nl;
    float acc = bs[j];
#pragma unroll
    for (int c = 0; c < 16; c++) acc = fmaf(xs[nl][c], ws[c * 64 + j], acc);
    g_h[n * 64 + j] = acc;
}

// ---------------------------------------------------------------------------
// Degree helpers
// ---------------------------------------------------------------------------
__global__ void zero_deg_kernel() {
    int i = blockIdx.x * 256 + threadIdx.x;
    if (i < NN) g_deg[i] = 0.0f;
}

__global__ void count_deg_kernel(const void* __restrict__ ei) {
    int e = blockIdx.x * 256 + threadIdx.x;
    int src, dst;
    load_edge(ei, e, src, dst);
    atomicAdd(&g_deg[dst], 1.0f);
}

// ---------------------------------------------------------------------------
// A = h @ w0[0:64,:],  B = h @ w0[64:128,:].  Also zeroes g_agg for its rows
// (replaces the separate zero_agg pass; runs before edge_kernel each block).
// ---------------------------------------------------------------------------
__global__ __launch_bounds__(256) void nodeAB_kernel(const float* __restrict__ w0k) {
    __shared__ float w0s[128 * 64];  // 32 KB
    __shared__ float hs[16][64];
    int tid = threadIdx.x;
    for (int i = tid; i < 128 * 64; i += 256) w0s[i] = w0k[i];
    int n0 = blockIdx.x * 16;
    for (int i = tid; i < 16 * 64; i += 256)
        hs[i >> 6][i & 63] = g_h[(n0 + (i >> 6)) * 64 + (i & 63)];
    // zero this block's slice of g_agg (16 rows x 64 = 1024 floats)
    {
        float4 z = make_float4(0.f, 0.f, 0.f, 0.f);
        ((float4*)(g_agg + n0 * 64))[tid] = z;  // 256 threads x 16B = 4 KB exact
    }
    __syncthreads();
    int j = tid & 63, grp = tid >> 6;
    float a[4] = {0, 0, 0, 0}, bb[4] = {0, 0, 0, 0};
#pragma unroll 8
    for (int c = 0; c < 64; c++) {
        float wa = w0s[c * 64 + j];
        float wb = w0s[(64 + c) * 64 + j];
#pragma unroll
        for (int i = 0; i < 4; i++) {
            float hv = hs[grp * 4 + i][c];
            a[i]  = fmaf(hv, wa, a[i]);
            bb[i] = fmaf(hv, wb, bb[i]);
        }
    }
#pragma unroll
    for (int i = 0; i < 4; i++) {
        int n = n0 + grp * 4 + i;
        g_A[n * 64 + j] = a[i];
        g_B[n * 64 + j] = bb[i];
    }
}

// ---------------------------------------------------------------------------
// Edge kernel (R1 structure, f32x2 inner loop).
//   t = relu(A[src] + B[dst] + b0)   — t[64] in registers
//   u = relu(t @ w1 + b1)            — w1 in SMEM (broadcast LDS.128),
//                                      u accumulated as packed fma.rn.f32x2
//   agg[dst] += u                    — red.global.add.v4.f32, 16/edge
// One thread per edge, 256 threads/block, grid 3125 (exact).
// ---------------------------------------------------------------------------
__global__ __launch_bounds__(256) void edge_kernel(const void* __restrict__ ei,
                                                   const float* __restrict__ w1,
                                                   const float* __restrict__ b0,
                                                   const float* __restrict__ b1) {
    __shared__ __align__(16) float w1s[64 * 64];  // 16 KB, unpadded (broadcast reads)
    __shared__ __align__(16) float b0s[64];
    __shared__ __align__(16) float b1s[64];
    int tid = threadIdx.x;
    for (int i = tid; i < 64 * 64; i += 256) w1s[i] = w1[i];
    if (tid < 64) { b0s[tid] = b0[tid]; b1s[tid] = b1[tid]; }
    __syncthreads();

    int e = blockIdx.x * 256 + tid;
    int src, dst;
    load_edge(ei, e, src, dst);

    const float4* Ar = (const float4*)(g_A + src * 64);
    const float4* Br = (const float4*)(g_B + dst * 64);

    float t[64];
#pragma unroll
    for (int q = 0; q < 16; q++) {
        float4 a = __ldg(&Ar[q]);
        float4 b = __ldg(&Br[q]);
        float4 c = ((const float4*)b0s)[q];
        t[4 * q + 0] = fmaxf(a.x + b.x + c.x, 0.0f);
        t[4 * q + 1] = fmaxf(a.y + b.y + c.y, 0.0f);
        t[4 * q + 2] = fmaxf(a.z + b.z + c.z, 0.0f);
        t[4 * q + 3] = fmaxf(a.w + b.w + c.w, 0.0f);
    }

    float* outp = g_agg + dst * 64;
    // 4 output groups of 16; u as 8 packed f32x2 accumulators per group
#pragma unroll 1
    for (int jgrp = 0; jgrp < 4; jgrp++) {
        unsigned long long u[8];
        const unsigned long long* b1p = (const unsigned long long*)(b1s + jgrp * 16);
#pragma unroll
        for (int i = 0; i < 8; i++) u[i] = b1p[i];

#pragma unroll
        for (int k = 0; k < 64; k++) {
            float tk = t[k];
            unsigned long long tk2;
            asm("mov.b64 %0, {%1, %2};" : "=l"(tk2) : "f"(tk), "f"(tk));
            const ulonglong2* wp = (const ulonglong2*)(w1s + k * 64 + jgrp * 16);
            ulonglong2 w01 = wp[0];  // broadcast LDS.128
            ulonglong2 w23 = wp[1];  // broadcast LDS.128
            ffma2(u[0], tk2, w01.x);
            ffma2(u[1], tk2, w01.y);
            ffma2(u[2], tk2, w23.x);
            ffma2(u[3], tk2, w23.y);
            const ulonglong2* wp2 = wp + 2;
            ulonglong2 w45 = wp2[0];
            ulonglong2 w67 = wp2[1];
            ffma2(u[4], tk2, w45.x);
            ffma2(u[5], tk2, w45.y);
            ffma2(u[6], tk2, w67.x);
            ffma2(u[7], tk2, w67.y);
        }

        // relu + scatter (4 x red.v4 per group)
#pragma unroll
        for (int i = 0; i < 4; i++) {
            float2 p0 = *reinterpret_cast<float2*>(&u[2 * i + 0]);
            float2 p1 = *reinterpret_cast<float2*>(&u[2 * i + 1]);
            float r0 = fmaxf(p0.x, 0.0f), r1 = fmaxf(p0.y, 0.0f);
            float r2 = fmaxf(p1.x, 0.0f), r3 = fmaxf(p1.y, 0.0f);
            float* d4 = outp + jgrp * 16 + 4 * i;
            asm volatile("red.global.add.v4.f32 [%0], {%1, %2, %3, %4};"
                         :: "l"(d4), "f"(r0), "f"(r1), "f"(r2), "f"(r3)
                         : "memory");
        }
    }
}

// ---------------------------------------------------------------------------
// h = agg @ w2 + deg * b2   ([50000,64] @ [64,64])
// ---------------------------------------------------------------------------
__global__ __launch_bounds__(256) void nodeOut_kernel(const float* __restrict__ w2k,
                                                      const float* __restrict__ b2k) {
    __shared__ float ws[64 * 64];
    __shared__ float hs[16][64];
    __shared__ float bs[64];
    int tid = threadIdx.x;
    for (int i = tid; i < 64 * 64; i += 256) ws[i] = w2k[i];
    if (tid < 64) bs[tid] = b2k[tid];
    int n0 = blockIdx.x * 16;
    for (int i = tid; i < 16 * 64; i += 256)
        hs[i >> 6][i & 63] = g_agg[(n0 + (i >> 6)) * 64 + (i & 63)];
    __syncthreads();
    int j = tid & 63, grp = tid >> 6;
    float acc[4];
#pragma unroll
    for (int i = 0; i < 4; i++) acc[i] = g_deg[n0 + grp * 4 + i] * bs[j];
#pragma unroll 8
    for (int c = 0; c < 64; c++) {
        float wv = ws[c * 64 + j];
#pragma unroll
        for (int i = 0; i < 4; i++)
            acc[i] = fmaf(hs[grp * 4 + i][c], wv, acc[i]);
    }
#pragma unroll
    for (int i = 0; i < 4; i++)
        g_h[(n0 + grp * 4 + i) * 64 + j] = acc[i];
}

// ---------------------------------------------------------------------------
// out = h @ lin_out_w + lin_out_b   ([50000,64] @ [64,16])
// ---------------------------------------------------------------------------
__global__ void lin_out_kernel(const float* __restrict__ w,
                               const float* __restrict__ b,
                               float* __restrict__ out) {
    __shared__ float ws[64 * 16];
    __shared__ float bs[16];
    __shared__ float hs[16][64];
    int tid = threadIdx.x;
    for (int i = tid; i < 64 * 16; i += 256) ws[i] = w[i];
    if (tid < 16) bs[tid] = b[tid];
    int n0 = blockIdx.x * 16;
    for (int i = tid; i < 16 * 64; i += 256)
        hs[i >> 6][i & 63] = g_h[(n0 + (i >> 6)) * 64 + (i & 63)];
    __syncthreads();
    int j = tid & 15, nl = tid >> 4;
    float acc = bs[j];
#pragma unroll 16
    for (int c = 0; c < 64; c++)
        acc = fmaf(hs[nl][c], ws[c * 16 + j], acc);
    out[(n0 + nl) * 16 + j] = acc;
}

// ---------------------------------------------------------------------------
// Launch.  Ordered so edge_kernel is the 4th launch (both prior ncu captures
// profiled launch #4; this round we want the edge kernel's profile).
// ---------------------------------------------------------------------------
extern "C" void kernel_launch(void* const* d_in, const int* in_sizes, int n_in,
                              void* d_out, int out_size) {
    const float* x        = (const float*)d_in[0];
    // d_in[1] = lframes (unused by the reference)
    const void*  ei       = d_in[2];
    const float* lin_in_w = (const float*)d_in[3];
    const float* lin_in_b = (const float*)d_in[4];
    const float* w0       = (const float*)d_in[5];
    const float* b0       = (const float*)d_in[6];
    const float* w1       = (const float*)d_in[7];
    const float* b1       = (const float*)d_in[8];
    const float* w2       = (const float*)d_in[9];
    const float* b2       = (const float*)d_in[10];
    const float* low      = (const float*)d_in[11];
    const float* lob      = (const float*)d_in[12];
    float* out = (float*)d_out;

    detect_kernel<<<1, 256>>>((const int*)ei);                       // 1
    lin_in_kernel<<<NN / 4, 256>>>(x, lin_in_w, lin_in_b);           // 2

    // block 0 (nodeAB zeroes g_agg)
    nodeAB_kernel<<<NN / 16, 256>>>(w0);                             // 3
    edge_kernel<<<NE / 256, 256>>>(ei, w1, b0, b1);                  // 4 <- profile
    zero_deg_kernel<<<(NN + 255) / 256, 256>>>();                    // 5
    count_deg_kernel<<<NE / 256, 256>>>(ei);                         // 6
    nodeOut_kernel<<<NN / 16, 256>>>(w2, b2);                        // 7

    for (int k = 1; k < 4; k++) {
        nodeAB_kernel<<<NN / 16, 256>>>(w0 + k * 128 * 64);
        edge_kernel<<<NE / 256, 256>>>(ei, w1 + k * 64 * 64, b0 + k * 64, b1 + k * 64);
        nodeOut_kernel<<<NN / 16, 256>>>(w2 + k * 64 * 64, b2 + k * 64);
    }

    lin_out_kernel<<<NN / 16, 256>>>(low, lob, out);
}

// round 8
// speedup vs baseline: 1.7706x; 1.3625x over previous
#include <cuda_runtime.h>
#include <cstdint>

// Problem constants
#define NN 50000
#define NE 800000
#define DH 64

// Scratch (device globals: no allocation allowed)
__device__ float g_h[NN * DH];     // node features (current block input)
__device__ float g_A[NN * DH];     // h @ w0[:64]   (src half)
__device__ float g_B[NN * DH];     // h @ w0[64:]   (dst half)
__device__ float g_agg[NN * DH];   // scatter-accumulated u
__device__ float g_deg[NN];        // in-degree (float)
__device__ int   g_is64;           // edge_index dtype flag (1 = int64, 0 = int32)

// Packed fp32x2 FMA (sm_100+; only reachable via PTX)
__device__ __forceinline__ void ffma2(unsigned long long& d,
                                      unsigned long long a,
                                      unsigned long long b) {
    asm("fma.rn.f32x2 %0, %1, %2, %0;" : "+l"(d) : "l"(a), "l"(b));
}

// ---------------------------------------------------------------------------
// Detect whether edge_index is int64 or int32 (JAX may silently emit int32).
// ---------------------------------------------------------------------------
__global__ void detect_kernel(const int* __restrict__ ei32) {
    __shared__ int any;
    if (threadIdx.x == 0) any = 0;
    __syncthreads();
    for (int i = threadIdx.x; i < 4096; i += 256) {
        if (ei32[2 * i + 1] != 0) any = 1;  // benign race
    }
    __syncthreads();
    if (threadIdx.x == 0) g_is64 = (any == 0) ? 1 : 0;
}

__device__ __forceinline__ void load_edge(const void* ei, int e, int& src, int& dst) {
    if (g_is64) {
        const long long* p = (const long long*)ei;
        src = (int)p[e];
        dst = (int)p[NE + e];
    } else {
        const int* p = (const int*)ei;
        src = p[e];
        dst = p[NE + e];
    }
}

// ---------------------------------------------------------------------------
// h = x @ lin_in_w + lin_in_b   ([50000,16] @ [16,64])
// ---------------------------------------------------------------------------
__global__ void lin_in_kernel(const float* __restrict__ x,
                              const float* __restrict__ w,
                              const float* __restrict__ b) {
    __shared__ float ws[16 * 64];
    __shared__ float bs[64];
    __shared__ float xs[4][16];
    int tid = threadIdx.x;
    for (int i = tid; i < 16 * 64; i += 256) ws[i] = w[i];
    if (tid < 64) bs[tid] = b[tid];
    if (tid < 64) {
        int nl = tid >> 4, c = tid & 15;
        int n = blockIdx.x * 4 + nl;
        xs[nl][c] = x[n * 16 + c];
    }
    __syncthreads();
    int j = tid & 63, nl = tid >> 6;
    int n = blockIdx.x * 4 + nl;
    float acc = bs[j];
#pragma unroll
    for (int c = 0; c < 16; c++) acc = fmaf(xs[nl][c], ws[c * 64 + j], acc);
    g_h[n * 64 + j] = acc;
}

// ---------------------------------------------------------------------------
// Degree helpers
// ---------------------------------------------------------------------------
__global__ void zero_deg_kernel() {
    int i = blockIdx.x * 256 + threadIdx.x;
    if (i < NN) g_deg[i] = 0.0f;
}

__global__ void count_deg_kernel(const void* __restrict__ ei) {
    int e = blockIdx.x * 256 + threadIdx.x;
    int src, dst;
    load_edge(ei, e, src, dst);
    atomicAdd(&g_deg[dst], 1.0f);
}

// ---------------------------------------------------------------------------
// A = h @ w0[0:64,:],  B = h @ w0[64:128,:].  Also zeroes g_agg for its rows.
// ---------------------------------------------------------------------------
__global__ __launch_bounds__(256) void nodeAB_kernel(const float* __restrict__ w0k) {
    __shared__ float w0s[128 * 64];  // 32 KB
    __shared__ float hs[16][64];
    int tid = threadIdx.x;
    for (int i = tid; i < 128 * 64; i += 256) w0s[i] = w0k[i];
    int n0 = blockIdx.x * 16;
    for (int i = tid; i < 16 * 64; i += 256)
        hs[i >> 6][i & 63] = g_h[(n0 + (i >> 6)) * 64 + (i & 63)];
    {
        float4 z = make_float4(0.f, 0.f, 0.f, 0.f);
        ((float4*)(g_agg + n0 * 64))[tid] = z;  // 256 threads x 16B = 4 KB exact
    }
    __syncthreads();
    int j = tid & 63, grp = tid >> 6;
    float a[4] = {0, 0, 0, 0}, bb[4] = {0, 0, 0, 0};
#pragma unroll 8
    for (int c = 0; c < 64; c++) {
        float wa = w0s[c * 64 + j];
        float wb = w0s[(64 + c) * 64 + j];
#pragma unroll
        for (int i = 0; i < 4; i++) {
            float hv = hs[grp * 4 + i][c];
            a[i]  = fmaf(hv, wa, a[i]);
            bb[i] = fmaf(hv, wb, bb[i]);
        }
    }
#pragma unroll
    for (int i = 0; i < 4; i++) {
        int n = n0 + grp * 4 + i;
        g_A[n * 64 + j] = a[i];
        g_B[n * 64 + j] = bb[i];
    }
}

// ---------------------------------------------------------------------------
// Edge kernel: TWO edges per thread; each w1 SMEM load amortized over both.
//   t = relu(A[src] + B[dst] + b0)   — t0[64], t1[64] in registers
//   u = relu(t @ w1 + b1)            — w1 in SMEM (broadcast LDS.128),
//                                      f32x2 accumulators, shared w loads
//   agg[dst] += u                    — red.global.add.v4.f32, 16/edge
// 128 threads/block = 256 edges/block. Grid 3125 (exact).
// ---------------------------------------------------------------------------
__global__ __launch_bounds__(128) void edge_kernel(const void* __restrict__ ei,
                                                   const float* __restrict__ w1,
                                                   const float* __restrict__ b0,
                                                   const float* __restrict__ b1) {
    __shared__ __align__(16) float w1s[64 * 64];  // 16 KB, unpadded (broadcast reads)
    __shared__ __align__(16) float b0s[64];
    __shared__ __align__(16) float b1s[64];
    int tid = threadIdx.x;
    for (int i = tid; i < 64 * 64; i += 128) w1s[i] = w1[i];
    if (tid < 64) { b0s[tid] = b0[tid]; b1s[tid] = b1[tid]; }
    __syncthreads();

    int e0 = blockIdx.x * 256 + tid;
    int e1 = e0 + 128;
    int src0, dst0, src1, dst1;
    load_edge(ei, e0, src0, dst0);
    load_edge(ei, e1, src1, dst1);

    const float4* Ar0 = (const float4*)(g_A + src0 * 64);
    const float4* Br0 = (const float4*)(g_B + dst0 * 64);
    const float4* Ar1 = (const float4*)(g_A + src1 * 64);
    const float4* Br1 = (const float4*)(g_B + dst1 * 64);

    float t0[64], t1[64];
#pragma unroll
    for (int q = 0; q < 16; q++) {
        float4 c = ((const float4*)b0s)[q];
        float4 a = __ldg(&Ar0[q]);
        float4 b = __ldg(&Br0[q]);
        t0[4 * q + 0] = fmaxf(a.x + b.x + c.x, 0.0f);
        t0[4 * q + 1] = fmaxf(a.y + b.y + c.y, 0.0f);
        t0[4 * q + 2] = fmaxf(a.z + b.z + c.z, 0.0f);
        t0[4 * q + 3] = fmaxf(a.w + b.w + c.w, 0.0f);
        float4 a1 = __ldg(&Ar1[q]);
        float4 b1v = __ldg(&Br1[q]);
        t1[4 * q + 0] = fmaxf(a1.x + b1v.x + c.x, 0.0f);
        t1[4 * q + 1] = fmaxf(a1.y + b1v.y + c.y, 0.0f);
        t1[4 * q + 2] = fmaxf(a1.z + b1v.z + c.z, 0.0f);
        t1[4 * q + 3] = fmaxf(a1.w + b1v.w + c.w, 0.0f);
    }

    float* outp0 = g_agg + dst0 * 64;
    float* outp1 = g_agg + dst1 * 64;

    // 4 output groups of 16; per group: u0[8], u1[8] packed f32x2 accumulators.
#pragma unroll 1
    for (int jgrp = 0; jgrp < 4; jgrp++) {
        unsigned long long u0[8], u1[8];
        const unsigned long long* b1p = (const unsigned long long*)(b1s + jgrp * 16);
#pragma unroll
        for (int i = 0; i < 8; i++) { u0[i] = b1p[i]; u1[i] = b1p[i]; }

#pragma unroll
        for (int k = 0; k < 64; k++) {
            unsigned long long tk0, tk1;
            asm("mov.b64 %0, {%1, %1};" : "=l"(tk0) : "f"(t0[k]));
            asm("mov.b64 %0, {%1, %1};" : "=l"(tk1) : "f"(t1[k]));
            const ulonglong2* wp = (const ulonglong2*)(w1s + k * 64 + jgrp * 16);
            ulonglong2 w01 = wp[0];  // broadcast LDS.128 — shared by both edges
            ulonglong2 w23 = wp[1];
            ffma2(u0[0], tk0, w01.x);  ffma2(u1[0], tk1, w01.x);
            ffma2(u0[1], tk0, w01.y);  ffma2(u1[1], tk1, w01.y);
            ffma2(u0[2], tk0, w23.x);  ffma2(u1[2], tk1, w23.x);
            ffma2(u0[3], tk0, w23.y);  ffma2(u1[3], tk1, w23.y);
            ulonglong2 w45 = wp[2];
            ulonglong2 w67 = wp[3];
            ffma2(u0[4], tk0, w45.x);  ffma2(u1[4], tk1, w45.x);
            ffma2(u0[5], tk0, w45.y);  ffma2(u1[5], tk1, w45.y);
            ffma2(u0[6], tk0, w67.x);  ffma2(u1[6], tk1, w67.x);
            ffma2(u0[7], tk0, w67.y);  ffma2(u1[7], tk1, w67.y);
        }

        // relu + scatter for both edges
#pragma unroll
        for (int i = 0; i < 4; i++) {
            float2 p0 = *reinterpret_cast<float2*>(&u0[2 * i + 0]);
            float2 p1 = *reinterpret_cast<float2*>(&u0[2 * i + 1]);
            float r0 = fmaxf(p0.x, 0.0f), r1 = fmaxf(p0.y, 0.0f);
            float r2 = fmaxf(p1.x, 0.0f), r3 = fmaxf(p1.y, 0.0f);
            float* d4 = outp0 + jgrp * 16 + 4 * i;
            asm volatile("red.global.add.v4.f32 [%0], {%1, %2, %3, %4};"
                         :: "l"(d4), "f"(r0), "f"(r1), "f"(r2), "f"(r3)
                         : "memory");
        }
#pragma unroll
        for (int i = 0; i < 4; i++) {
            float2 p0 = *reinterpret_cast<float2*>(&u1[2 * i + 0]);
            float2 p1 = *reinterpret_cast<float2*>(&u1[2 * i + 1]);
            float r0 = fmaxf(p0.x, 0.0f), r1 = fmaxf(p0.y, 0.0f);
            float r2 = fmaxf(p1.x, 0.0f), r3 = fmaxf(p1.y, 0.0f);
            float* d4 = outp1 + jgrp * 16 + 4 * i;
            asm volatile("red.global.add.v4.f32 [%0], {%1, %2, %3, %4};"
                         :: "l"(d4), "f"(r0), "f"(r1), "f"(r2), "f"(r3)
                         : "memory");
        }
    }
}

// ---------------------------------------------------------------------------
// h = agg @ w2 + deg * b2   ([50000,64] @ [64,64])
// ---------------------------------------------------------------------------
__global__ __launch_bounds__(256) void nodeOut_kernel(const float* __restrict__ w2k,
                                                      const float* __restrict__ b2k) {
    __shared__ float ws[64 * 64];
    __shared__ float hs[16][64];
    __shared__ float bs[64];
    int tid = threadIdx.x;
    for (int i = tid; i < 64 * 64; i += 256) ws[i] = w2k[i];
    if (tid < 64) bs[tid] = b2k[tid];
    int n0 = blockIdx.x * 16;
    for (int i = tid; i < 16 * 64; i += 256)
        hs[i >> 6][i & 63] = g_agg[(n0 + (i >> 6)) * 64 + (i & 63)];
    __syncthreads();
    int j = tid & 63, grp = tid >> 6;
    float acc[4];
#pragma unroll
    for (int i = 0; i < 4; i++) acc[i] = g_deg[n0 + grp * 4 + i] * bs[j];
#pragma unroll 8
    for (int c = 0; c < 64; c++) {
        float wv = ws[c * 64 + j];
#pragma unroll
        for (int i = 0; i < 4; i++)
            acc[i] = fmaf(hs[grp * 4 + i][c], wv, acc[i]);
    }
#pragma unroll
    for (int i = 0; i < 4; i++)
        g_h[(n0 + grp * 4 + i) * 64 + j] = acc[i];
}

// ---------------------------------------------------------------------------
// out = h @ lin_out_w + lin_out_b   ([50000,64] @ [64,16])
// ---------------------------------------------------------------------------
__global__ void lin_out_kernel(const float* __restrict__ w,
                               const float* __restrict__ b,
                               float* __restrict__ out) {
    __shared__ float ws[64 * 16];
    __shared__ float bs[16];
    __shared__ float hs[16][64];
    int tid = threadIdx.x;
    for (int i = tid; i < 64 * 16; i += 256) ws[i] = w[i];
    if (tid < 16) bs[tid] = b[tid];
    int n0 = blockIdx.x * 16;
    for (int i = tid; i < 16 * 64; i += 256)
        hs[i >> 6][i & 63] = g_h[(n0 + (i >> 6)) * 64 + (i & 63)];
    __syncthreads();
    int j = tid & 15, nl = tid >> 4;
    float acc = bs[j];
#pragma unroll 16
    for (int c = 0; c < 64; c++)
        acc = fmaf(hs[nl][c], ws[c * 16 + j], acc);
    out[(n0 + nl) * 16 + j] = acc;
}

// ---------------------------------------------------------------------------
// Launch.  edge_kernel kept at launch #4 (ncu captures launch #4).
// ---------------------------------------------------------------------------
extern "C" void kernel_launch(void* const* d_in, const int* in_sizes, int n_in,
                              void* d_out, int out_size) {
    const float* x        = (const float*)d_in[0];
    // d_in[1] = lframes (unused by the reference)
    const void*  ei       = d_in[2];
    const float* lin_in_w = (const float*)d_in[3];
    const float* lin_in_b = (const float*)d_in[4];
    const float* w0       = (const float*)d_in[5];
    const float* b0       = (const float*)d_in[6];
    const float* w1       = (const float*)d_in[7];
    const float* b1       = (const float*)d_in[8];
    const float* w2       = (const float*)d_in[9];
    const float* b2       = (const float*)d_in[10];
    const float* low      = (const float*)d_in[11];
    const float* lob      = (const float*)d_in[12];
    float* out = (float*)d_out;

    detect_kernel<<<1, 256>>>((const int*)ei);                       // 1
    lin_in_kernel<<<NN / 4, 256>>>(x, lin_in_w, lin_in_b);           // 2

    // block 0 (nodeAB zeroes g_agg)
    nodeAB_kernel<<<NN / 16, 256>>>(w0);                             // 3
    edge_kernel<<<NE / 256, 128>>>(ei, w1, b0, b1);                  // 4 <- profile
    zero_deg_kernel<<<(NN + 255) / 256, 256>>>();                    // 5
    count_deg_kernel<<<NE / 256, 256>>>(ei);                         // 6
    nodeOut_kernel<<<NN / 16, 256>>>(w2, b2);                        // 7

    for (int k = 1; k < 4; k++) {
        nodeAB_kernel<<<NN / 16, 256>>>(w0 + k * 128 * 64);
        edge_kernel<<<NE / 256, 128>>>(ei, w1 + k * 64 * 64, b0 + k * 64, b1 + k * 64);
        nodeOut_kernel<<<NN / 16, 256>>>(w2 + k * 64 * 64, b2 + k * 64);
    }

    lin_out_kernel<<<NN / 16, 256>>>(low, lob, out);
}

// round 11
// speedup vs baseline: 2.2562x; 1.2742x over previous
#include <cuda_runtime.h>
#include <cuda_bf16.h>
#include <cstdint>

#define NN 50000
#define NE 800000

// Scratch (device globals: no allocation allowed)
__device__ float g_h[NN * 64];
__device__ float g_A[NN * 64];
__device__ float g_B[NN * 64];
__device__ float g_agg[NN * 64];
__device__ float g_deg[NN];
__device__ int   g_is64;
// Per-layer w1 transposed + bf16-split, padded: hi[64 rows][36 words] then lo.
// 4608 words per layer.
__device__ uint32_t g_w1t[4 * 4608];

// ---------------------------------------------------------------------------
// Edge-index dtype handling
// ---------------------------------------------------------------------------
__device__ __forceinline__ void load_edge(const void* ei, int e, int& src, int& dst) {
    if (g_is64) {
        const long long* p = (const long long*)ei;
        src = (int)p[e];
        dst = (int)p[NE + e];
    } else {
        const int* p = (const int*)ei;
        src = p[e];
        dst = p[NE + e];
    }
}

// ---------------------------------------------------------------------------
// prep_kernel: block 0 detects edge dtype; blocks 1..4 build w1T hi/lo
// (transpose [k][j] -> [j][k], split fp32 = bf16_hi + bf16_lo, 36-word rows)
// ---------------------------------------------------------------------------
__global__ void prep_kernel(const int* __restrict__ ei32,
                            const float* __restrict__ w1all) {
    __shared__ int any;
    if (blockIdx.x == 0) {
        if (threadIdx.x == 0) any = 0;
        __syncthreads();
        for (int i = threadIdx.x; i < 4096; i += 256)
            if (ei32[2 * i + 1] != 0) any = 1;
        __syncthreads();
        if (threadIdx.x == 0) g_is64 = (any == 0) ? 1 : 0;
    } else {
        int layer = blockIdx.x - 1;
        const float* w1 = w1all + layer * 4096;
        __nv_bfloat16* gw = (__nv_bfloat16*)(g_w1t + layer * 4608);
        for (int i = threadIdx.x; i < 4096; i += 256) {
            int k = i >> 6, j = i & 63;
            float w = w1[i];
            __nv_bfloat16 h = __float2bfloat16(w);
            __nv_bfloat16 l = __float2bfloat16(w - __bfloat162float(h));
            gw[j * 72 + k] = h;            // hi: row j (72 halves = 36 words)
            gw[4608 + j * 72 + k] = l;     // lo block starts at word 2304
        }
    }
}

// ---------------------------------------------------------------------------
// h = x @ lin_in_w + lin_in_b   ([50000,16] @ [16,64])
// ---------------------------------------------------------------------------
__global__ void lin_in_kernel(const float* __restrict__ x,
                              const float* __restrict__ w,
                              const float* __restrict__ b) {
    __shared__ float ws[16 * 64];
    __shared__ float bs[64];
    __shared__ float xs[4][16];
    int tid = threadIdx.x;
    for (int i = tid; i < 16 * 64; i += 256) ws[i] = w[i];
    if (tid < 64) bs[tid] = b[tid];
    if (tid < 64) {
        int nl = tid >> 4, c = tid & 15;
        int n = blockIdx.x * 4 + nl;
        xs[nl][c] = x[n * 16 + c];
    }
    __syncthreads();
    int j = tid & 63, nl = tid >> 6;
    int n = blockIdx.x * 4 + nl;
    float acc = bs[j];
#pragma unroll
    for (int c = 0; c < 16; c++) acc = fmaf(xs[nl][c], ws[c * 64 + j], acc);
    g_h[n * 64 + j] = acc;
}

__global__ void zero_deg_kernel() {
    int i = blockIdx.x * 256 + threadIdx.x;
    if (i < NN) g_deg[i] = 0.0f;
}

__global__ void count_deg_kernel(const void* __restrict__ ei) {
    int e = blockIdx.x * 256 + threadIdx.x;
    int src, dst;
    load_edge(ei, e, src, dst);
    atomicAdd(&g_deg[dst], 1.0f);
}

// ---------------------------------------------------------------------------
// A = h @ w0[0:64,:],  B = h @ w0[64:128,:].  Also zeroes g_agg rows.
// ---------------------------------------------------------------------------
__global__ __launch_bounds__(256) void nodeAB_kernel(const float* __restrict__ w0k) {
    __shared__ float w0s[128 * 64];
    __shared__ float hs[16][64];
    int tid = threadIdx.x;
    for (int i = tid; i < 128 * 64; i += 256) w0s[i] = w0k[i];
    int n0 = blockIdx.x * 16;
    for (int i = tid; i < 16 * 64; i += 256)
        hs[i >> 6][i & 63] = g_h[(n0 + (i >> 6)) * 64 + (i & 63)];
    {
        float4 z = make_float4(0.f, 0.f, 0.f, 0.f);
        ((float4*)(g_agg + n0 * 64))[tid] = z;
    }
    __syncthreads();
    int j = tid & 63, grp = tid >> 6;
    float a[4] = {0, 0, 0, 0}, bb[4] = {0, 0, 0, 0};
#pragma unroll 8
    for (int c = 0; c < 64; c++) {
        float wa = w0s[c * 64 + j];
        float wb = w0s[(64 + c) * 64 + j];
#pragma unroll
        for (int i = 0; i < 4; i++) {
            float hv = hs[grp * 4 + i][c];
            a[i]  = fmaf(hv, wa, a[i]);
            bb[i] = fmaf(hv, wb, bb[i]);
        }
    }
#pragma unroll
    for (int i = 0; i < 4; i++) {
        int n = n0 + grp * 4 + i;
        g_A[n * 64 + j] = a[i];
        g_B[n * 64 + j] = bb[i];
    }
}

// ---------------------------------------------------------------------------
// HMMA helper: mma.sync.m16n8k16 row.col f32.bf16.bf16.f32
// ---------------------------------------------------------------------------
__device__ __forceinline__ void mma16816(float* c, const uint32_t* a, const uint32_t* b) {
    asm volatile(
        "mma.sync.aligned.m16n8k16.row.col.f32.bf16.bf16.f32 "
        "{%0,%1,%2,%3}, {%4,%5,%6,%7}, {%8,%9}, {%0,%1,%2,%3};"
        : "+f"(c[0]), "+f"(c[1]), "+f"(c[2]), "+f"(c[3])
        : "r"(a[0]), "r"(a[1]), "r"(a[2]), "r"(a[3]), "r"(b[0]), "r"(b[1]));
}

// ---------------------------------------------------------------------------
// Edge MMA kernel. 128 threads = 4 warps; each warp owns 32 edges (M=32).
//   gather:  t = relu(A[src]+B[dst]+b0), bf16 hi/lo -> per-warp SMEM stage
//   GEMM:    u = t @ w1 via m16n8k16 bf16, 3-term split precision, fp32 acc
//   epilogue: +b1, relu, transpose via stage overlay, red.global.add.v4
// SMEM: b0s 256 | b1s 256 | W1 hi+lo 18432 | 4 x warp stage 9216  = 55808
// Stage per warp (2304 words): t_hi rows [e*36], t_lo [1152+e*36];
// overlaid later as fp32 epilogue rows [e*72] (A frags are in regs by then).
// ---------------------------------------------------------------------------
#define EMM_SMEM 55808

__global__ __launch_bounds__(128) void edge_mma_kernel(const void* __restrict__ ei,
                                                       int layer,
                                                       const float* __restrict__ b0,
                                                       const float* __restrict__ b1) {
    extern __shared__ char smem[];
    float* b0s = (float*)smem;
    float* b1s = (float*)(smem + 256);
    uint32_t* W1 = (uint32_t*)(smem + 512);          // hi [64][36], lo at +2304
    int tid = threadIdx.x, warp = tid >> 5, lane = tid & 31;
    uint32_t* W = (uint32_t*)(smem + 18944) + warp * 2304;

    if (tid < 64) { b0s[tid] = b0[tid]; b1s[tid] = b1[tid]; }
    {
        const uint4* src = (const uint4*)(g_w1t + layer * 4608);
        uint4* dst = (uint4*)W1;
        for (int i = tid; i < 1152; i += 128) dst[i] = src[i];
    }
    __syncthreads();

    int e_tile = blockIdx.x * 128 + warp * 32;
    int ln4 = lane >> 2, q = lane & 3;

    // ---- gather + relu + bf16 split into stage (4 passes x 8 edges) ----
#pragma unroll 1
    for (int p = 0; p < 4; p++) {
        int el = p * 8 + ln4;
        int s_, d_;
        load_edge(ei, e_tile + el, s_, d_);
        const float4* Ar = (const float4*)(g_A + s_ * 64) + q * 4;
        const float4* Br = (const float4*)(g_B + d_ * 64) + q * 4;
        uint32_t hp[8], lp[8];
#pragma unroll
        for (int i = 0; i < 4; i++) {
            float4 a = __ldg(Ar + i), b = __ldg(Br + i);
            float4 c = ((const float4*)b0s)[q * 4 + i];
            float tv[4] = {fmaxf(a.x + b.x + c.x, 0.f), fmaxf(a.y + b.y + c.y, 0.f),
                           fmaxf(a.z + b.z + c.z, 0.f), fmaxf(a.w + b.w + c.w, 0.f)};
#pragma unroll
            for (int m2 = 0; m2 < 2; m2++) {
                float v0 = tv[2 * m2], v1 = tv[2 * m2 + 1];
                __nv_bfloat16 h0 = __float2bfloat16(v0);
                __nv_bfloat16 h1 = __float2bfloat16(v1);
                __nv_bfloat16 l0 = __float2bfloat16(v0 - __bfloat162float(h0));
                __nv_bfloat16 l1 = __float2bfloat16(v1 - __bfloat162float(h1));
                hp[i * 2 + m2] = (uint32_t)__bfloat16_as_ushort(h0) |
                                 ((uint32_t)__bfloat16_as_ushort(h1) << 16);
                lp[i * 2 + m2] = (uint32_t)__bfloat16_as_ushort(l0) |
                                 ((uint32_t)__bfloat16_as_ushort(l1) << 16);
            }
        }
        uint32_t base = el * 36 + q * 8;
        *(uint4*)(W + base)            = make_uint4(hp[0], hp[1], hp[2], hp[3]);
        *(uint4*)(W + base + 4)        = make_uint4(hp[4], hp[5], hp[6], hp[7]);
        *(uint4*)(W + 1152 + base)     = make_uint4(lp[0], lp[1], lp[2], lp[3]);
        *(uint4*)(W + 1152 + base + 4) = make_uint4(lp[4], lp[5], lp[6], lp[7]);
    }
    __syncwarp();

    // ---- load all A fragments into registers (64 regs) ----
    // Af[mt][v][kt][r]: m-tile (16 rows), version hi/lo, k-tile (16), 4 regs
    uint32_t Af[2][2][4][4];
#pragma unroll
    for (int mt = 0; mt < 2; mt++)
#pragma unroll
        for (int v = 0; v < 2; v++)
#pragma unroll
            for (int kt = 0; kt < 4; kt++) {
                int r0 = mt * 16 + ln4;
                int w0i = v * 1152 + r0 * 36 + kt * 8 + q;
                int w1i = v * 1152 + (r0 + 8) * 36 + kt * 8 + q;
                Af[mt][v][kt][0] = W[w0i];
                Af[mt][v][kt][1] = W[w1i];
                Af[mt][v][kt][2] = W[w0i + 4];
                Af[mt][v][kt][3] = W[w1i + 4];
            }
    __syncwarp();

    // ---- GEMM over 8 n-tiles; epilogue into stage overlay (fp32 rows e*72) ----
    float* ep = (float*)W;
#pragma unroll 1
    for (int nt = 0; nt < 8; nt++) {
        uint32_t Bh[4][2], Bl[4][2];
        int nrow = nt * 8 + ln4;
#pragma unroll
        for (int kt = 0; kt < 4; kt++) {
            int wi = nrow * 36 + kt * 8 + q;
            Bh[kt][0] = W1[wi];        Bh[kt][1] = W1[wi + 4];
            Bl[kt][0] = W1[2304 + wi]; Bl[kt][1] = W1[2304 + wi + 4];
        }
        int col = nt * 8 + q * 2;
        float bias0 = b1s[col], bias1 = b1s[col + 1];
        float C[2][4];
#pragma unroll
        for (int mt = 0; mt < 2; mt++) {
            C[mt][0] = bias0; C[mt][1] = bias1; C[mt][2] = bias0; C[mt][3] = bias1;
        }
#pragma unroll
        for (int kt = 0; kt < 4; kt++)
#pragma unroll
            for (int mt = 0; mt < 2; mt++) {
                mma16816(C[mt], Af[mt][0][kt], Bh[kt]);  // hi*hi
                mma16816(C[mt], Af[mt][0][kt], Bl[kt]);  // hi*lo
                mma16816(C[mt], Af[mt][1][kt], Bh[kt]);  // lo*hi
            }
#pragma unroll
        for (int mt = 0; mt < 2; mt++) {
            int r = mt * 16 + ln4;
            float2 v01 = make_float2(fmaxf(C[mt][0], 0.f), fmaxf(C[mt][1], 0.f));
            float2 v23 = make_float2(fmaxf(C[mt][2], 0.f), fmaxf(C[mt][3], 0.f));
            *(float2*)(ep + r * 72 + nt * 8 + q * 2)       = v01;
            *(float2*)(ep + (r + 8) * 72 + nt * 8 + q * 2) = v23;
        }
    }
    __syncwarp();

    // ---- scatter: 4 passes x 8 edges, 4 lanes/edge, red.global.add.v4 ----
#pragma unroll 1
    for (int p = 0; p < 4; p++) {
        int el = p * 8 + ln4;
        int s_, d_;
        load_edge(ei, e_tile + el, s_, d_);
        float* outp = g_agg + d_ * 64 + q * 16;
        const float4* row = (const float4*)(ep + el * 72 + q * 16);
#pragma unroll
        for (int i = 0; i < 4; i++) {
            float4 v = row[i];
            asm volatile("red.global.add.v4.f32 [%0], {%1, %2, %3, %4};"
                         :: "l"(outp + 4 * i), "f"(v.x), "f"(v.y), "f"(v.z), "f"(v.w)
                         : "memory");
        }
    }
}

// ---------------------------------------------------------------------------
// h = agg @ w2 + deg * b2   ([50000,64] @ [64,64])
// ---------------------------------------------------------------------------
__global__ __launch_bounds__(256) void nodeOut_kernel(const float* __restrict__ w2k,
                                                      const float* __restrict__ b2k) {
    __shared__ float ws[64 * 64];
    __shared__ float hs[16][64];
    __shared__ float bs[64];
    int tid = threadIdx.x;
    for (int i = tid; i < 64 * 64; i += 256) ws[i] = w2k[i];
    if (tid < 64) bs[tid] = b2k[tid];
    int n0 = blockIdx.x * 16;
    for (int i = tid; i < 16 * 64; i += 256)
        hs[i >> 6][i & 63] = g_agg[(n0 + (i >> 6)) * 64 + (i & 63)];
    __syncthreads();
    int j = tid & 63, grp = tid >> 6;
    float acc[4];
#pragma unroll
    for (int i = 0; i < 4; i++) acc[i] = g_deg[n0 + grp * 4 + i] * bs[j];
#pragma unroll 8
    for (int c = 0; c < 64; c++) {
        float wv = ws[c * 64 + j];
#pragma unroll
        for (int i = 0; i < 4; i++)
            acc[i] = fmaf(hs[grp * 4 + i][c], wv, acc[i]);
    }
#pragma unroll
    for (int i = 0; i < 4; i++)
        g_h[(n0 + grp * 4 + i) * 64 + j] = acc[i];
}

// ---------------------------------------------------------------------------
// out = h @ lin_out_w + lin_out_b   ([50000,64] @ [64,16])
// ---------------------------------------------------------------------------
__global__ void lin_out_kernel(const float* __restrict__ w,
                               const float* __restrict__ b,
                               float* __restrict__ out) {
    __shared__ float ws[64 * 16];
    __shared__ float bs[16];
    __shared__ float hs[16][64];
    int tid = threadIdx.x;
    for (int i = tid; i < 64 * 16; i += 256) ws[i] = w[i];
    if (tid < 16) bs[tid] = b[tid];
    int n0 = blockIdx.x * 16;
    for (int i = tid; i < 16 * 64; i += 256)
        hs[i >> 6][i & 63] = g_h[(n0 + (i >> 6)) * 64 + (i & 63)];
    __syncthreads();
    int j = tid & 15, nl = tid >> 4;
    float acc = bs[j];
#pragma unroll 16
    for (int c = 0; c < 64; c++)
        acc = fmaf(hs[nl][c], ws[c * 16 + j], acc);
    out[(n0 + nl) * 16 + j] = acc;
}

// ---------------------------------------------------------------------------
// Launch.  edge_mma_kernel at launch #4 (ncu captures launch #4).
// ---------------------------------------------------------------------------
extern "C" void kernel_launch(void* const* d_in, const int* in_sizes, int n_in,
                              void* d_out, int out_size) {
    const float* x        = (const float*)d_in[0];
    // d_in[1] = lframes (unused by the reference)
    const void*  ei       = d_in[2];
    const float* lin_in_w = (const float*)d_in[3];
    const float* lin_in_b = (const float*)d_in[4];
    const float* w0       = (const float*)d_in[5];
    const float* b0       = (const float*)d_in[6];
    const float* w1       = (const float*)d_in[7];
    const float* b1       = (const float*)d_in[8];
    const float* w2       = (const float*)d_in[9];
    const float* b2       = (const float*)d_in[10];
    const float* low      = (const float*)d_in[11];
    const float* lob      = (const float*)d_in[12];
    float* out = (float*)d_out;

    cudaFuncSetAttribute(edge_mma_kernel,
                         cudaFuncAttributeMaxDynamicSharedMemorySize, EMM_SMEM);

    prep_kernel<<<5, 256>>>((const int*)ei, w1);                        // 1
    lin_in_kernel<<<NN / 4, 256>>>(x, lin_in_w, lin_in_b);              // 2

    nodeAB_kernel<<<NN / 16, 256>>>(w0);                                // 3
    edge_mma_kernel<<<NE / 128, 128, EMM_SMEM>>>(ei, 0, b0, b1);        // 4 <- profile
    zero_deg_kernel<<<(NN + 255) / 256, 256>>>();                       // 5
    count_deg_kernel<<<NE / 256, 256>>>(ei);                            // 6
    nodeOut_kernel<<<NN / 16, 256>>>(w2, b2);                           // 7

    for (int k = 1; k < 4; k++) {
        nodeAB_kernel<<<NN / 16, 256>>>(w0 + k * 128 * 64);
        edge_mma_kernel<<<NE / 128, 128, EMM_SMEM>>>(ei, k, b0 + k * 64, b1 + k * 64);
        nodeOut_kernel<<<NN / 16, 256>>>(w2 + k * 64 * 64, b2 + k * 64);
    }

    lin_out_kernel<<<NN / 16, 256>>>(low, lob, out);
}

// round 14
// speedup vs baseline: 2.6717x; 1.1842x over previous
#include <cuda_runtime.h>
#include <cuda_bf16.h>
#include <cstdint>

#define NN 50000
#define NE 800000

// Scratch (device globals: no allocation allowed)
__device__ float g_h[NN * 64];
__device__ float g_A[NN * 64];
__device__ float g_B[NN * 64];
__device__ float g_agg[NN * 64];
__device__ float g_deg[NN];
__device__ int   g_is64;
// Per-layer w1 transposed + bf16-split, padded: hi[64 rows][36 words] then lo.
__device__ uint32_t g_w1t[4 * 4608];

// ---------------------------------------------------------------------------
// Edge-index dtype handling
// ---------------------------------------------------------------------------
__device__ __forceinline__ void load_edge(const void* ei, int e, int& src, int& dst) {
    if (g_is64) {
        const long long* p = (const long long*)ei;
        src = (int)p[e];
        dst = (int)p[NE + e];
    } else {
        const int* p = (const int*)ei;
        src = p[e];
        dst = p[NE + e];
    }
}

// ---------------------------------------------------------------------------
// prep_kernel: block 0 detects edge dtype; blocks 1..4 build w1T hi/lo
// ---------------------------------------------------------------------------
__global__ void prep_kernel(const int* __restrict__ ei32,
                            const float* __restrict__ w1all) {
    __shared__ int any;
    if (blockIdx.x == 0) {
        if (threadIdx.x == 0) any = 0;
        __syncthreads();
        for (int i = threadIdx.x; i < 4096; i += 256)
            if (ei32[2 * i + 1] != 0) any = 1;
        __syncthreads();
        if (threadIdx.x == 0) g_is64 = (any == 0) ? 1 : 0;
    } else {
        int layer = blockIdx.x - 1;
        const float* w1 = w1all + layer * 4096;
        __nv_bfloat16* gw = (__nv_bfloat16*)(g_w1t + layer * 4608);
        for (int i = threadIdx.x; i < 4096; i += 256) {
            int k = i >> 6, j = i & 63;
            float w = w1[i];
            __nv_bfloat16 h = __float2bfloat16(w);
            __nv_bfloat16 l = __float2bfloat16(w - __bfloat162float(h));
            gw[j * 72 + k] = h;
            gw[4608 + j * 72 + k] = l;
        }
    }
}

// ---------------------------------------------------------------------------
// h = x @ lin_in_w + lin_in_b   ([50000,16] @ [16,64])
// ---------------------------------------------------------------------------
__global__ void lin_in_kernel(const float* __restrict__ x,
                              const float* __restrict__ w,
                              const float* __restrict__ b) {
    __shared__ float ws[16 * 64];
    __shared__ float bs[64];
    __shared__ float xs[4][16];
    int tid = threadIdx.x;
    for (int i = tid; i < 16 * 64; i += 256) ws[i] = w[i];
    if (tid < 64) bs[tid] = b[tid];
    if (tid < 64) {
        int nl = tid >> 4, c = tid & 15;
        int n = blockIdx.x * 4 + nl;
        xs[nl][c] = x[n * 16 + c];
    }
    __syncthreads();
    int j = tid & 63, nl = tid >> 6;
    int n = blockIdx.x * 4 + nl;
    float acc = bs[j];
#pragma unroll
    for (int c = 0; c < 16; c++) acc = fmaf(xs[nl][c], ws[c * 64 + j], acc);
    g_h[n * 64 + j] = acc;
}

__global__ void zero_deg_kernel() {
    int i = blockIdx.x * 256 + threadIdx.x;
    if (i < NN) g_deg[i] = 0.0f;
}

__global__ void count_deg_kernel(const void* __restrict__ ei) {
    int e = blockIdx.x * 256 + threadIdx.x;
    int src, dst;
    load_edge(ei, e, src, dst);
    atomicAdd(&g_deg[dst], 1.0f);
}

// ---------------------------------------------------------------------------
// A = h @ w0[0:64,:],  B = h @ w0[64:128,:].  Also zeroes g_agg rows.
// ---------------------------------------------------------------------------
__global__ __launch_bounds__(256) void nodeAB_kernel(const float* __restrict__ w0k) {
    __shared__ float w0s[128 * 64];
    __shared__ float hs[16][64];
    int tid = threadIdx.x;
    for (int i = tid; i < 128 * 64; i += 256) w0s[i] = w0k[i];
    int n0 = blockIdx.x * 16;
    for (int i = tid; i < 16 * 64; i += 256)
        hs[i >> 6][i & 63] = g_h[(n0 + (i >> 6)) * 64 + (i & 63)];
    {
        float4 z = make_float4(0.f, 0.f, 0.f, 0.f);
        ((float4*)(g_agg + n0 * 64))[tid] = z;
    }
    __syncthreads();
    int j = tid & 63, grp = tid >> 6;
    float a[4] = {0, 0, 0, 0}, bb[4] = {0, 0, 0, 0};
#pragma unroll 8
    for (int c = 0; c < 64; c++) {
        float wa = w0s[c * 64 + j];
        float wb = w0s[(64 + c) * 64 + j];
#pragma unroll
        for (int i = 0; i < 4; i++) {
            float hv = hs[grp * 4 + i][c];
            a[i]  = fmaf(hv, wa, a[i]);
            bb[i] = fmaf(hv, wb, bb[i]);
        }
    }
#pragma unroll
    for (int i = 0; i < 4; i++) {
        int n = n0 + grp * 4 + i;
        g_A[n * 64 + j] = a[i];
        g_B[n * 64 + j] = bb[i];
    }
}

// ---------------------------------------------------------------------------
// HMMA helper: mma.sync.m16n8k16 row.col f32.bf16.bf16.f32
// ---------------------------------------------------------------------------
__device__ __forceinline__ void mma16816(float* c, const uint32_t* a, const uint32_t* b) {
    asm volatile(
        "mma.sync.aligned.m16n8k16.row.col.f32.bf16.bf16.f32 "
        "{%0,%1,%2,%3}, {%4,%5,%6,%7}, {%8,%9}, {%0,%1,%2,%3};"
        : "+f"(c[0]), "+f"(c[1]), "+f"(c[2]), "+f"(c[3])
        : "r"(a[0]), "r"(a[1]), "r"(a[2]), "r"(a[3]), "r"(b[0]), "r"(b[1]));
}

// ---------------------------------------------------------------------------
// Edge MMA kernel. 128 threads = 4 warps; each warp owns 32 edges (M=32).
// COALESCED gather/scatter: lane (e,q) step i touches bytes [i*64 + q*16)
// of each node row, so every warp instruction covers one contiguous 64B
// segment per row (8 wavefronts/instr instead of 16).
// SMEM: b0s 256 | b1s 256 | W1 hi+lo 18432 | 4 x warp stage 9216 = 55808
// ---------------------------------------------------------------------------
#define EMM_SMEM 55808

__global__ __launch_bounds__(128) void edge_mma_kernel(const void* __restrict__ ei,
                                                       int layer,
                                                       const float* __restrict__ b0,
                                                       const float* __restrict__ b1) {
    extern __shared__ char smem[];
    float* b0s = (float*)smem;
    float* b1s = (float*)(smem + 256);
    uint32_t* W1 = (uint32_t*)(smem + 512);          // hi [64][36], lo at +2304
    int tid = threadIdx.x, warp = tid >> 5, lane = tid & 31;
    uint32_t* W = (uint32_t*)(smem + 18944) + warp * 2304;

    if (tid < 64) { b0s[tid] = b0[tid]; b1s[tid] = b1[tid]; }
    {
        const uint4* src = (const uint4*)(g_w1t + layer * 4608);
        uint4* dst = (uint4*)W1;
        for (int i = tid; i < 1152; i += 128) dst[i] = src[i];
    }
    __syncthreads();

    int e_tile = blockIdx.x * 128 + warp * 32;
    int ln4 = lane >> 2, q = lane & 3;

    // ---- gather + relu + bf16 split into stage (4 passes x 8 edges) ----
    // step i: lane (e,q) loads float4 at element offset (i*4+q)*4 -> elements
    // i*16 + q*4 + {0..3}; staged at word el*36 + i*8 + q*2 (uint2 hi/lo).
#pragma unroll 1
    for (int p = 0; p < 4; p++) {
        int el = p * 8 + ln4;
        int s_, d_;
        load_edge(ei, e_tile + el, s_, d_);
        const float4* Ar = (const float4*)(g_A + s_ * 64) + q;
        const float4* Br = (const float4*)(g_B + d_ * 64) + q;
#pragma unroll
        for (int i = 0; i < 4; i++) {
            float4 a = __ldg(Ar + i * 4);
            float4 b = __ldg(Br + i * 4);
            float4 c = ((const float4*)b0s)[i * 4 + q];
            float v0 = fmaxf(a.x + b.x + c.x, 0.f);
            float v1 = fmaxf(a.y + b.y + c.y, 0.f);
            float v2 = fmaxf(a.z + b.z + c.z, 0.f);
            float v3 = fmaxf(a.w + b.w + c.w, 0.f);
            __nv_bfloat16 h0 = __float2bfloat16(v0), h1 = __float2bfloat16(v1);
            __nv_bfloat16 h2 = __float2bfloat16(v2), h3 = __float2bfloat16(v3);
            __nv_bfloat16 l0 = __float2bfloat16(v0 - __bfloat162float(h0));
            __nv_bfloat16 l1 = __float2bfloat16(v1 - __bfloat162float(h1));
            __nv_bfloat16 l2 = __float2bfloat16(v2 - __bfloat162float(h2));
            __nv_bfloat16 l3 = __float2bfloat16(v3 - __bfloat162float(h3));
            uint32_t hw0 = (uint32_t)__bfloat16_as_ushort(h0) |
                           ((uint32_t)__bfloat16_as_ushort(h1) << 16);
            uint32_t hw1 = (uint32_t)__bfloat16_as_ushort(h2) |
                           ((uint32_t)__bfloat16_as_ushort(h3) << 16);
            uint32_t lw0 = (uint32_t)__bfloat16_as_ushort(l0) |
                           ((uint32_t)__bfloat16_as_ushort(l1) << 16);
            uint32_t lw1 = (uint32_t)__bfloat16_as_ushort(l2) |
                           ((uint32_t)__bfloat16_as_ushort(l3) << 16);
            uint32_t base = (uint32_t)(el * 36 + i * 8 + q * 2);
            *(uint2*)(W + base)        = make_uint2(hw0, hw1);
            *(uint2*)(W + 1152 + base) = make_uint2(lw0, lw1);
        }
    }
    __syncwarp();

    // ---- load all A fragments into registers ----
    uint32_t Af[2][2][4][4];
#pragma unroll
    for (int mt = 0; mt < 2; mt++)
#pragma unroll
        for (int v = 0; v < 2; v++)
#pragma unroll
            for (int kt = 0; kt < 4; kt++) {
                int r0 = mt * 16 + ln4;
                int w0i = v * 1152 + r0 * 36 + kt * 8 + q;
                int w1i = v * 1152 + (r0 + 8) * 36 + kt * 8 + q;
                Af[mt][v][kt][0] = W[w0i];
                Af[mt][v][kt][1] = W[w1i];
                Af[mt][v][kt][2] = W[w0i + 4];
                Af[mt][v][kt][3] = W[w1i + 4];
            }
    __syncwarp();

    // ---- GEMM over 8 n-tiles; epilogue into stage overlay (fp32 rows e*72) ----
    float* ep = (float*)W;
#pragma unroll 1
    for (int nt = 0; nt < 8; nt++) {
        uint32_t Bh[4][2], Bl[4][2];
        int nrow = nt * 8 + ln4;
#pragma unroll
        for (int kt = 0; kt < 4; kt++) {
            int wi = nrow * 36 + kt * 8 + q;
            Bh[kt][0] = W1[wi];        Bh[kt][1] = W1[wi + 4];
            Bl[kt][0] = W1[2304 + wi]; Bl[kt][1] = W1[2304 + wi + 4];
        }
        int col = nt * 8 + q * 2;
        float bias0 = b1s[col], bias1 = b1s[col + 1];
        float C[2][4];
#pragma unroll
        for (int mt = 0; mt < 2; mt++) {
            C[mt][0] = bias0; C[mt][1] = bias1; C[mt][2] = bias0; C[mt][3] = bias1;
        }
#pragma unroll
        for (int kt = 0; kt < 4; kt++)
#pragma unroll
            for (int mt = 0; mt < 2; mt++) {
                mma16816(C[mt], Af[mt][0][kt], Bh[kt]);
                mma16816(C[mt], Af[mt][0][kt], Bl[kt]);
                mma16816(C[mt], Af[mt][1][kt], Bh[kt]);
            }
#pragma unroll
        for (int mt = 0; mt < 2; mt++) {
            int r = mt * 16 + ln4;
            float2 v01 = make_float2(fmaxf(C[mt][0], 0.f), fmaxf(C[mt][1], 0.f));
            float2 v23 = make_float2(fmaxf(C[mt][2], 0.f), fmaxf(C[mt][3], 0.f));
            *(float2*)(ep + r * 72 + nt * 8 + q * 2)       = v01;
            *(float2*)(ep + (r + 8) * 72 + nt * 8 + q * 2) = v23;
        }
    }
    __syncwarp();

    // ---- scatter: coalesced — step i covers bytes [i*64 + q*16) per edge ----
#pragma unroll 1
    for (int p = 0; p < 4; p++) {
        int el = p * 8 + ln4;
        int s_, d_;
        load_edge(ei, e_tile + el, s_, d_);
        float* outp = g_agg + d_ * 64;
#pragma unroll
        for (int i = 0; i < 4; i++) {
            float4 v = *(const float4*)(ep + el * 72 + i * 16 + q * 4);
            asm volatile("red.global.add.v4.f32 [%0], {%1, %2, %3, %4};"
                         :: "l"(outp + i * 16 + q * 4),
                            "f"(v.x), "f"(v.y), "f"(v.z), "f"(v.w)
                         : "memory");
        }
    }
}

// ---------------------------------------------------------------------------
// h = agg @ w2 + deg * b2   ([50000,64] @ [64,64])
// ---------------------------------------------------------------------------
__global__ __launch_bounds__(256) void nodeOut_kernel(const float* __restrict__ w2k,
                                                      const float* __restrict__ b2k) {
    __shared__ float ws[64 * 64];
    __shared__ float hs[16][64];
    __shared__ float bs[64];
    int tid = threadIdx.x;
    for (int i = tid; i < 64 * 64; i += 256) ws[i] = w2k[i];
    if (tid < 64) bs[tid] = b2k[tid];
    int n0 = blockIdx.x * 16;
    for (int i = tid; i < 16 * 64; i += 256)
        hs[i >> 6][i & 63] = g_agg[(n0 + (i >> 6)) * 64 + (i & 63)];
    __syncthreads();
    int j = tid & 63, grp = tid >> 6;
    float acc[4];
#pragma unroll
    for (int i = 0; i < 4; i++) acc[i] = g_deg[n0 + grp * 4 + i] * bs[j];
#pragma unroll 8
    for (int c = 0; c < 64; c++) {
        float wv = ws[c * 64 + j];
#pragma unroll
        for (int i = 0; i < 4; i++)
            acc[i] = fmaf(hs[grp * 4 + i][c], wv, acc[i]);
    }
#pragma unroll
    for (int i = 0; i < 4; i++)
        g_h[(n0 + grp * 4 + i) * 64 + j] = acc[i];
}

// ---------------------------------------------------------------------------
// out = h @ lin_out_w + lin_out_b   ([50000,64] @ [64,16])
// ---------------------------------------------------------------------------
__global__ void lin_out_kernel(const float* __restrict__ w,
                               const float* __restrict__ b,
                               float* __restrict__ out) {
    __shared__ float ws[64 * 16];
    __shared__ float bs[16];
    __shared__ float hs[16][64];
    int tid = threadIdx.x;
    for (int i = tid; i < 64 * 16; i += 256) ws[i] = w[i];
    if (tid < 16) bs[tid] = b[tid];
    int n0 = blockIdx.x * 16;
    for (int i = tid; i < 16 * 64; i += 256)
        hs[i >> 6][i & 63] = g_h[(n0 + (i >> 6)) * 64 + (i & 63)];
    __syncthreads();
    int j = tid & 15, nl = tid >> 4;
    float acc = bs[j];
#pragma unroll 16
    for (int c = 0; c < 64; c++)
        acc = fmaf(hs[nl][c], ws[c * 16 + j], acc);
    out[(n0 + nl) * 16 + j] = acc;
}

// ---------------------------------------------------------------------------
// Launch.  edge_mma_kernel at launch #4 (ncu captures launch #4).
// ---------------------------------------------------------------------------
extern "C" void kernel_launch(void* const* d_in, const int* in_sizes, int n_in,
                              void* d_out, int out_size) {
    const float* x        = (const float*)d_in[0];
    // d_in[1] = lframes (unused by the reference)
    const void*  ei       = d_in[2];
    const float* lin_in_w = (const float*)d_in[3];
    const float* lin_in_b = (const float*)d_in[4];
    const float* w0       = (const float*)d_in[5];
    const float* b0       = (const float*)d_in[6];
    const float* w1       = (const float*)d_in[7];
    const float* b1       = (const float*)d_in[8];
    const float* w2       = (const float*)d_in[9];
    const float* b2       = (const float*)d_in[10];
    const float* low      = (const float*)d_in[11];
    const float* lob      = (const float*)d_in[12];
    float* out = (float*)d_out;

    cudaFuncSetAttribute(edge_mma_kernel,
                         cudaFuncAttributeMaxDynamicSharedMemorySize, EMM_SMEM);

    prep_kernel<<<5, 256>>>((const int*)ei, w1);                        // 1
    lin_in_kernel<<<NN / 4, 256>>>(x, lin_in_w, lin_in_b);              // 2

    nodeAB_kernel<<<NN / 16, 256>>>(w0);                                // 3
    edge_mma_kernel<<<NE / 128, 128, EMM_SMEM>>>(ei, 0, b0, b1);        // 4 <- profile
    zero_deg_kernel<<<(NN + 255) / 256, 256>>>();                       // 5
    count_deg_kernel<<<NE / 256, 256>>>(ei);                            // 6
    nodeOut_kernel<<<NN / 16, 256>>>(w2, b2);                           // 7

    for (int k = 1; k < 4; k++) {
        nodeAB_kernel<<<NN / 16, 256>>>(w0 + k * 128 * 64);
        edge_mma_kernel<<<NE / 128, 128, EMM_SMEM>>>(ei, k, b0 + k * 64, b1 + k * 64);
        nodeOut_kernel<<<NN / 16, 256>>>(w2 + k * 64 * 64, b2 + k * 64);
    }

    lin_out_kernel<<<NN / 16, 256>>>(low, lob, out);
}